// round 5
// baseline (speedup 1.0000x reference)
#include <cuda_runtime.h>

#define H 512
#define W 512
#define MASK 511
#define NPLANE (H * W)
#define NTH 256
#define NBLK 128                 // <= 148 SMs: all co-resident, software barrier safe

#define FSTRIDE 580              // float2 stride per sub-FFT (bank-offset 8f)
#define PAD(i) ((i) + ((i) >> 3))

__device__ float  g_partial[2 * NPLANE];
__device__ float2 g_Fhat[NPLANE];

// ------------------------------------------------------------- grid barrier
__device__ volatile unsigned g_bar_gen = 0;
__device__ unsigned g_bar_count = 0;

__device__ __forceinline__ void gridbar() {
    __syncthreads();
    if (threadIdx.x == 0) {
        unsigned my = g_bar_gen;
        __threadfence();
        unsigned old = atomicAdd(&g_bar_count, 1);
        if (old == NBLK - 1) {
            atomicExch(&g_bar_count, 0);
            __threadfence();
            atomicAdd((unsigned*)&g_bar_gen, 1);
        } else {
            while (g_bar_gen == my) { }
        }
        __threadfence();
    }
    __syncthreads();
}

// ------------------------------------------------------------- complex ops
__device__ __forceinline__ float2 cmul(float2 a, float2 b) {
    return make_float2(a.x * b.x - a.y * b.y, a.x * b.y + a.y * b.x);
}
__device__ __forceinline__ float2 cadd(float2 a, float2 b) { return make_float2(a.x + b.x, a.y + b.y); }
__device__ __forceinline__ float2 csub(float2 a, float2 b) { return make_float2(a.x - b.x, a.y - b.y); }

// 8-point DFT, natural order, constant twiddles. SIGN=-1 forward.
template <int SIGN>
__device__ __forceinline__ void dft8(const float2* a, float2* y) {
    const float C = 0.70710678118654752f;
    const float S = (float)SIGN;
    float2 u[8], v[8];
#pragma unroll
    for (int p = 0; p < 4; ++p) {
        float2 A = a[p], B = a[p + 4];
        float2 d = csub(A, B);
        u[2 * p] = cadd(A, B);
        float2 w = (p == 0) ? make_float2(1.f, 0.f)
                 : (p == 1) ? make_float2(C, S * C)
                 : (p == 2) ? make_float2(0.f, S)
                            : make_float2(-C, S * C);
        u[2 * p + 1] = cmul(d, w);
    }
#pragma unroll
    for (int tt = 0; tt < 4; ++tt) {
        int p = tt >> 1, q = tt & 1;
        float2 A = u[q + 2 * p], B = u[q + 2 * p + 4];
        float2 d = csub(A, B);
        v[q + 4 * p] = cadd(A, B);
        v[q + 4 * p + 2] = (p == 0) ? d : cmul(d, make_float2(0.f, S));
    }
#pragma unroll
    for (int q = 0; q < 4; ++q) {
        float2 A = v[q], B = v[q + 4];
        y[q] = cadd(A, B);
        y[q + 4] = csub(A, B);
    }
}

// 512-pt radix-8 Stockham FFT; 64 threads/FFT, 8 elems in registers.
// x[e] holds element (t + 64e) in, bin (t + 64e) out. 2 syncthreads.
template <int SIGN>
__device__ __forceinline__ void fft512_r8(float2* x, float2* sA, float2* sB, int t) {
    float2 y[8];
    dft8<SIGN>(x, y);
    {
        float base = (float)SIGN * 0.012271846303085130f * (float)t;   // 2π/512·t
#pragma unroll
        for (int e = 1; e < 8; ++e) {
            float sn, cs;
            __sincosf(base * (float)e, &sn, &cs);
            y[e] = cmul(y[e], make_float2(cs, sn));
        }
#pragma unroll
        for (int e = 0; e < 8; ++e) sA[PAD(8 * t + e)] = y[e];
    }
    __syncthreads();
#pragma unroll
    for (int e = 0; e < 8; ++e) x[e] = sA[PAD(t + 64 * e)];
    dft8<SIGN>(x, y);
    {
        int p = t >> 3, q = t & 7;
        float base = (float)SIGN * 0.098174770424681f * (float)p;      // 2π/64·p
#pragma unroll
        for (int e = 1; e < 8; ++e) {
            float sn, cs;
            __sincosf(base * (float)e, &sn, &cs);
            y[e] = cmul(y[e], make_float2(cs, sn));
        }
        int wb = 8 * t - 7 * q;
#pragma unroll
        for (int e = 0; e < 8; ++e) sB[PAD(wb + 8 * e)] = y[e];
    }
    __syncthreads();
#pragma unroll
    for (int e = 0; e < 8; ++e) x[e] = sB[PAD(t + 64 * e)];
    dft8<SIGN>(x, y);
#pragma unroll
    for (int e = 0; e < 8; ++e) x[e] = y[e];
}

// Transfer function of 1000 Jacobi iterations (phi0 = B), incl. 1/N^2.
__device__ __forceinline__ float jacobi_T(int ki, int kj) {
    const float invN2 = 1.0f / 262144.0f;
    float sa = sinf(0.0061359231515f * (float)ki);
    float sb = sinf(0.0061359231515f * (float)kj);
    float oms = sa * sa + sb * sb;                   // 1 - s (no cancellation)
    if (oms <= 0.0f) return -249.0f * invN2;
    float arg = 500.0f * log1pf(-oms * (2.0f - oms));
    float s1000 = (arg < -87.0f) ? 0.0f : expf(arg);
    return (s1000 - (1.0f - s1000) / (4.0f * oms)) * invN2;
}

// ------------------------------------------------------------- fused kernel
__global__ void __launch_bounds__(NTH) k_fused(const float* __restrict__ X,
                                               const float* __restrict__ F,
                                               float* __restrict__ out) {
    __shared__ float2 sm[2 * 4 * FSTRIDE];
    const int tid = threadIdx.x;
    const int blk = blockIdx.x;
    const float NU = 0.1f;

    // ---- Phase 0: partial = -(v.grad)X + NU*lap(X) + F
#pragma unroll
    for (int e = 0; e < 8; ++e) {
        int id = blk * (NPLANE / NBLK) + e * NTH + tid;
        int i = id >> 9, j = id & MASK;
        int im = (i - 1) & MASK, ip = (i + 1) & MASK;
        int jm = (j - 1) & MASK, jp = (j + 1) & MASK;
        float u = X[id];
        float v = X[NPLANE + id];
#pragma unroll
        for (int c = 0; c < 2; ++c) {
            const float* xc = X + c * NPLANE;
            float ctr = xc[id];
            float up = xc[im * W + j];
            float dn = xc[ip * W + j];
            float lf = xc[i * W + jm];
            float rt = xc[i * W + jp];
            float dx = (dn - up) * 0.5f;
            float dy = (rt - lf) * 0.5f;
            float lap = (up + dn + lf + rt) - 4.0f * ctr;
            g_partial[c * NPLANE + id] = -(u * dx + v * dy) + NU * lap + F[c * NPLANE + id];
        }
    }
    gridbar();

    // ---- Phase A: B inline + forward row FFT -> g_Fhat
    {
        int f = tid >> 6, t = tid & 63;
        int r = blk * 4 + f;
        float2* sA = sm + f * FSTRIDE;
        float2* sB = sm + (4 + f) * FSTRIDE;
        const float* p0 = g_partial;
        const float* p1 = g_partial + NPLANE;
        int rp = (r + 1) & MASK, rm = (r - 1) & MASK;

        float2 x[8];
#pragma unroll
        for (int e = 0; e < 8; ++e) {
            int j = t + 64 * e;
            int jp = (j + 1) & MASK, jm = (j - 1) & MASK;
            float b = ((p0[rp * W + j] - p0[rm * W + j])
                     + (p1[r * W + jp] - p1[r * W + jm])) * 5.0f;   // RHO/(2·DX·DT)=5
            x[e] = make_float2(b, 0.0f);
        }
        fft512_r8<-1>(x, sA, sB, t);
#pragma unroll
        for (int e = 0; e < 8; ++e) g_Fhat[r * W + t + 64 * e] = x[e];
    }
    gridbar();

    // ---- Phase B: per-column fwd FFT, spectral multiply, inv FFT (in place)
    {
        int f = tid & 3, t = tid >> 2;
        int c = blk * 4 + f;
        float2* sA = sm + f * FSTRIDE;
        float2* sB = sm + (4 + f) * FSTRIDE;

        float2 x[8];
#pragma unroll
        for (int e = 0; e < 8; ++e) x[e] = g_Fhat[(t + 64 * e) * W + c];
        fft512_r8<-1>(x, sA, sB, t);

        float sy = __sinf(0.012271846303085130f * (float)c);
#pragma unroll
        for (int e = 0; e < 8; ++e) {
            int ki = t + 64 * e;
            float Tv = jacobi_T(ki, c);
            float sx = __sinf(0.012271846303085130f * (float)ki);
            x[e] = cmul(x[e], make_float2(-Tv * sy, Tv * sx));   // Zhat = phi_hat·(i·sx − sy)
        }
        fft512_r8<1>(x, sA, sB, t);
#pragma unroll
        for (int e = 0; e < 8; ++e) g_Fhat[(t + 64 * e) * W + c] = x[e];
    }
    gridbar();

    // ---- Phase C: inverse row FFT + epilogue
    {
        int f = tid >> 6, t = tid & 63;
        int r = blk * 4 + f;
        float2* sA = sm + f * FSTRIDE;
        float2* sB = sm + (4 + f) * FSTRIDE;

        float2 x[8];
#pragma unroll
        for (int e = 0; e < 8; ++e) x[e] = g_Fhat[r * W + t + 64 * e];
        fft512_r8<1>(x, sA, sB, t);
#pragma unroll
        for (int e = 0; e < 8; ++e) {
            int id = r * W + t + 64 * e;
            out[id]          = g_partial[id]          - x[e].x;    // gx = Re
            out[NPLANE + id] = g_partial[NPLANE + id] - x[e].y;    // gy = Im
        }
    }
}

extern "C" void kernel_launch(void* const* d_in, const int* in_sizes, int n_in,
                              void* d_out, int out_size) {
    const float* X = (const float*)d_in[1];
    const float* F = (const float*)d_in[2];
    float* out = (float*)d_out;
    k_fused<<<NBLK, NTH>>>(X, F, out);
}

// round 6
// speedup vs baseline: 1.2044x; 1.2044x over previous
#include <cuda_runtime.h>

#define H 512
#define W 512
#define MASK 511
#define NPLANE (H * W)
#define NTH 256

#define FSTRIDE 580              // float2 stride per sub-FFT (bank-offset 8f)
#define PAD(i) ((i) + ((i) >> 3))

__device__ float2 g_Fhat[NPLANE];

// ------------------------------------------------------------- complex ops
__device__ __forceinline__ float2 cmul(float2 a, float2 b) {
    return make_float2(a.x * b.x - a.y * b.y, a.x * b.y + a.y * b.x);
}
__device__ __forceinline__ float2 cadd(float2 a, float2 b) { return make_float2(a.x + b.x, a.y + b.y); }
__device__ __forceinline__ float2 csub(float2 a, float2 b) { return make_float2(a.x - b.x, a.y - b.y); }

// partial component c at (i,j), computed directly from X, F.
__device__ __forceinline__ float partial_c(const float* __restrict__ X,
                                           const float* __restrict__ F,
                                           int c, int i, int j) {
    int im = (i - 1) & MASK, ip = (i + 1) & MASK;
    int jm = (j - 1) & MASK, jp = (j + 1) & MASK;
    int id = i * W + j;
    const float* xc = X + c * NPLANE;
    float ctr = xc[id];
    float up = xc[im * W + j];
    float dn = xc[ip * W + j];
    float lf = xc[i * W + jm];
    float rt = xc[i * W + jp];
    float u = X[id];
    float v = X[NPLANE + id];
    float dx = (dn - up) * 0.5f;
    float dy = (rt - lf) * 0.5f;
    float lap = (up + dn + lf + rt) - 4.0f * ctr;
    return -(u * dx + v * dy) + 0.1f * lap + F[c * NPLANE + id];
}

// 8-point DFT, natural order, constant twiddles. SIGN=-1 forward.
template <int SIGN>
__device__ __forceinline__ void dft8(const float2* a, float2* y) {
    const float C = 0.70710678118654752f;
    const float S = (float)SIGN;
    float2 u[8], v[8];
#pragma unroll
    for (int p = 0; p < 4; ++p) {
        float2 A = a[p], B = a[p + 4];
        float2 d = csub(A, B);
        u[2 * p] = cadd(A, B);
        float2 w = (p == 0) ? make_float2(1.f, 0.f)
                 : (p == 1) ? make_float2(C, S * C)
                 : (p == 2) ? make_float2(0.f, S)
                            : make_float2(-C, S * C);
        u[2 * p + 1] = cmul(d, w);
    }
#pragma unroll
    for (int tt = 0; tt < 4; ++tt) {
        int p = tt >> 1, q = tt & 1;
        float2 A = u[q + 2 * p], B = u[q + 2 * p + 4];
        float2 d = csub(A, B);
        v[q + 4 * p] = cadd(A, B);
        v[q + 4 * p + 2] = (p == 0) ? d : cmul(d, make_float2(0.f, S));
    }
#pragma unroll
    for (int q = 0; q < 4; ++q) {
        float2 A = v[q], B = v[q + 4];
        y[q] = cadd(A, B);
        y[q + 4] = csub(A, B);
    }
}

// 512-pt radix-8 Stockham FFT; 64 threads/FFT, 8 elems in registers.
// x[e] holds element (t + 64e) in, bin (t + 64e) out. 2 syncthreads.
template <int SIGN>
__device__ __forceinline__ void fft512_r8(float2* x, float2* sA, float2* sB, int t) {
    float2 y[8];
    dft8<SIGN>(x, y);
    {
        float base = (float)SIGN * 0.012271846303085130f * (float)t;   // 2π/512·t
#pragma unroll
        for (int e = 1; e < 8; ++e) {
            float sn, cs;
            __sincosf(base * (float)e, &sn, &cs);
            y[e] = cmul(y[e], make_float2(cs, sn));
        }
#pragma unroll
        for (int e = 0; e < 8; ++e) sA[PAD(8 * t + e)] = y[e];
    }
    __syncthreads();
#pragma unroll
    for (int e = 0; e < 8; ++e) x[e] = sA[PAD(t + 64 * e)];
    dft8<SIGN>(x, y);
    {
        int p = t >> 3, q = t & 7;
        float base = (float)SIGN * 0.098174770424681f * (float)p;      // 2π/64·p
#pragma unroll
        for (int e = 1; e < 8; ++e) {
            float sn, cs;
            __sincosf(base * (float)e, &sn, &cs);
            y[e] = cmul(y[e], make_float2(cs, sn));
        }
        int wb = 8 * t - 7 * q;
#pragma unroll
        for (int e = 0; e < 8; ++e) sB[PAD(wb + 8 * e)] = y[e];
    }
    __syncthreads();
#pragma unroll
    for (int e = 0; e < 8; ++e) x[e] = sB[PAD(t + 64 * e)];
    dft8<SIGN>(x, y);
#pragma unroll
    for (int e = 0; e < 8; ++e) x[e] = y[e];
}

// Transfer function of 1000 Jacobi iterations (phi0 = B), incl. 1/N^2.
__device__ __forceinline__ float jacobi_T(int ki, int kj) {
    const float invN2 = 1.0f / 262144.0f;
    float sa = sinf(0.0061359231515f * (float)ki);
    float sb = sinf(0.0061359231515f * (float)kj);
    float oms = sa * sa + sb * sb;                   // 1 - s (no cancellation)
    if (oms <= 0.0f) return -249.0f * invN2;
    float arg = 500.0f * log1pf(-oms * (2.0f - oms));
    float s1000 = (arg < -87.0f) ? 0.0f : expf(arg);
    return (s1000 - (1.0f - s1000) / (4.0f * oms)) * invN2;
}

// ---------------------------------------------------------------- kernels
// K1: B computed directly from X,F (4 on-the-fly partial evals) + fwd row FFT.
__global__ void __launch_bounds__(NTH) k_rows_fwd(const float* __restrict__ X,
                                                  const float* __restrict__ F) {
    __shared__ float2 sm[2 * 4 * FSTRIDE];
    int f = threadIdx.x >> 6, t = threadIdx.x & 63;
    int r = blockIdx.x * 4 + f;
    float2* sA = sm + f * FSTRIDE;
    float2* sB = sm + (4 + f) * FSTRIDE;
    int rp = (r + 1) & MASK, rm = (r - 1) & MASK;

    float2 x[8];
#pragma unroll
    for (int e = 0; e < 8; ++e) {
        int j = t + 64 * e;
        int jp = (j + 1) & MASK, jm = (j - 1) & MASK;
        float b = ((partial_c(X, F, 0, rp, j) - partial_c(X, F, 0, rm, j))
                 + (partial_c(X, F, 1, r, jp) - partial_c(X, F, 1, r, jm))) * 5.0f;
        x[e] = make_float2(b, 0.0f);
    }
    fft512_r8<-1>(x, sA, sB, t);
#pragma unroll
    for (int e = 0; e < 8; ++e) g_Fhat[r * W + t + 64 * e] = x[e];
}

// K2: per-column fwd FFT, multiply by T·(i·sx − sy), inverse FFT (in place).
__global__ void __launch_bounds__(NTH) k_cols() {
    __shared__ float2 sm[2 * 4 * FSTRIDE];
    int f = threadIdx.x & 3, t = threadIdx.x >> 2;
    int c = blockIdx.x * 4 + f;
    float2* sA = sm + f * FSTRIDE;
    float2* sB = sm + (4 + f) * FSTRIDE;

    float2 x[8];
#pragma unroll
    for (int e = 0; e < 8; ++e) x[e] = g_Fhat[(t + 64 * e) * W + c];
    fft512_r8<-1>(x, sA, sB, t);

    float sy = __sinf(0.012271846303085130f * (float)c);
#pragma unroll
    for (int e = 0; e < 8; ++e) {
        int ki = t + 64 * e;
        float Tv = jacobi_T(ki, c);
        float sx = __sinf(0.012271846303085130f * (float)ki);
        x[e] = cmul(x[e], make_float2(-Tv * sy, Tv * sx));   // Zhat = phi_hat·(i·sx − sy)
    }
    fft512_r8<1>(x, sA, sB, t);
#pragma unroll
    for (int e = 0; e < 8; ++e) g_Fhat[(t + 64 * e) * W + c] = x[e];
}

// K3: inverse row FFT; out[c] = partial_c (recomputed) − (Re,Im)Z.
__global__ void __launch_bounds__(NTH) k_rows_inv_out(const float* __restrict__ X,
                                                      const float* __restrict__ F,
                                                      float* __restrict__ out) {
    __shared__ float2 sm[2 * 4 * FSTRIDE];
    int f = threadIdx.x >> 6, t = threadIdx.x & 63;
    int r = blockIdx.x * 4 + f;
    float2* sA = sm + f * FSTRIDE;
    float2* sB = sm + (4 + f) * FSTRIDE;

    float2 x[8];
#pragma unroll
    for (int e = 0; e < 8; ++e) x[e] = g_Fhat[r * W + t + 64 * e];
    fft512_r8<1>(x, sA, sB, t);
#pragma unroll
    for (int e = 0; e < 8; ++e) {
        int j = t + 64 * e;
        int id = r * W + j;
        out[id]          = partial_c(X, F, 0, r, j) - x[e].x;   // gx = Re
        out[NPLANE + id] = partial_c(X, F, 1, r, j) - x[e].y;   // gy = Im
    }
}

extern "C" void kernel_launch(void* const* d_in, const int* in_sizes, int n_in,
                              void* d_out, int out_size) {
    const float* X = (const float*)d_in[1];
    const float* F = (const float*)d_in[2];
    float* out = (float*)d_out;

    k_rows_fwd<<<H / 4, NTH>>>(X, F);
    k_cols<<<W / 4, NTH>>>();
    k_rows_inv_out<<<H / 4, NTH>>>(X, F, out);
}